// round 7
// baseline (speedup 1.0000x reference)
#include <cuda_runtime.h>
#include <cuda_bf16.h>
#include <cstdint>
#include <cstdio>

// Problem constants
#define BB 8
#define PP 16
#define SS 512
#define DD 512
#define HH 8
#define DEPTH 64
#define DFF 2048
#define VOC 10000
#define NROW 128              // B*P
#define SIGMA 0.1f
#define LN_EPS 1e-6f

// Output offsets (float elements)
static const size_t OFF_R4    = 0;
static const size_t OFF_Z     = 65536;
static const size_t OFF_AVGS  = 131072;
static const size_t OFF_GAVG  = 211072;
static const size_t OFF_MAXP  = 291072;
static const size_t OFF_EPSZ  = 371072;
static const size_t OFF_ATTNW = 436608;
static const size_t OFF_K     = 502144;
static const size_t OFF_V     = 502144ULL + 33554432ULL;
static const size_t OFF_WNEW  = 67611008ULL;
static const size_t OFF_INEW  = 67611136ULL;

// ---------------- device scratch ----------------
__device__ float g_q[NROW * DD];
__device__ float g_k[NROW * DD];
__device__ float g_v[NROW * DD];
__device__ float g_zattn[NROW * DD];
__device__ float g_z[NROW * DD];
__device__ float g_out1[NROW * DD];
__device__ float g_h[NROW * DFF];
__device__ float g_rr[NROW * DD];
__device__ float g_pred[NROW * VOC];
__device__ float g_part[3 * 4 * NROW * DD * 4];   // partial buffer
__device__ float g_rowmax[NROW];
__device__ float g_rowrsum[NROW];
__device__ float g_wsq[NROW];
__device__ float g_lw[NROW];                      // log(w + 1e-10)

// ---------------- packed f32x2 helpers ----------------
union F2U { float2 f; unsigned long long u; };

__device__ __forceinline__ unsigned long long fma2(unsigned long long a,
                                                   unsigned long long b,
                                                   unsigned long long c) {
    unsigned long long d;
    asm("fma.rn.f32x2 %0, %1, %2, %3;" : "=l"(d) : "l"(a), "l"(b), "l"(c));
    return d;
}

// ---------------- GEMM v3: double-buffered split-K (small GEMMs) ----------
struct GArgs {
    const float* A;
    const float* W;
    const float* bias;
    const float* eps;
    float* C;
};

#define GM 64
#define GN 64
#define GK 32

__global__ __launch_bounds__(256, 2)
void gemm2_kernel(GArgs g0, GArgs g1, GArgs g2, int M, int N, int K,
                  int ksplit, int klen, int mode, float* part) {
    int z = blockIdx.z;
    int gi = z / ksplit, kz = z - gi * ksplit;
    GArgs g = (gi == 0) ? g0 : (gi == 1) ? g1 : g2;

    __shared__ float2 As2[2][GK][GM];   // duplicated {a,a}; 32 KB
    __shared__ float  Ws[2][GK][GN];    // 16 KB  (total 48 KB)

    int tid = threadIdx.x;
    int tx = tid & 15, ty = tid >> 4;
    int m0 = blockIdx.y * GM;
    int n0 = blockIdx.x * GN;
    int kbase = kz * klen;

    unsigned long long acc[4][2];
#pragma unroll
    for (int i = 0; i < 4; i++) { acc[i][0] = 0ULL; acc[i][1] = 0ULL; }

    int arow = tid >> 3, akq = tid & 7;
    int wkk = tid >> 4, wnq = tid & 15;

    const float* Abase0 = &g.A[(size_t)(m0 + arow) * K + kbase + akq * 4];
    const float* Abase1 = &g.A[(size_t)(m0 + 32 + arow) * K + kbase + akq * 4];
    int ncol = n0 + wnq * 4;
    bool wok = (ncol < N);
    const float* Wbase0 = &g.W[(size_t)(kbase + wkk) * N + ncol];
    const float* Wbase1 = &g.W[(size_t)(kbase + 16 + wkk) * N + ncol];

    float4 ra0, ra1, rw0, rw1;

    ra0 = *(const float4*)(Abase0);
    ra1 = *(const float4*)(Abase1);
    rw0 = wok ? *(const float4*)(Wbase0) : make_float4(0.f, 0.f, 0.f, 0.f);
    rw1 = wok ? *(const float4*)(Wbase1) : make_float4(0.f, 0.f, 0.f, 0.f);
    {
        As2[0][akq * 4 + 0][arow] = make_float2(ra0.x, ra0.x);
        As2[0][akq * 4 + 1][arow] = make_float2(ra0.y, ra0.y);
        As2[0][akq * 4 + 2][arow] = make_float2(ra0.z, ra0.z);
        As2[0][akq * 4 + 3][arow] = make_float2(ra0.w, ra0.w);
        As2[0][akq * 4 + 0][arow + 32] = make_float2(ra1.x, ra1.x);
        As2[0][akq * 4 + 1][arow + 32] = make_float2(ra1.y, ra1.y);
        As2[0][akq * 4 + 2][arow + 32] = make_float2(ra1.z, ra1.z);
        As2[0][akq * 4 + 3][arow + 32] = make_float2(ra1.w, ra1.w);
        *(float4*)&Ws[0][wkk][wnq * 4] = rw0;
        *(float4*)&Ws[0][16 + wkk][wnq * 4] = rw1;
    }
    __syncthreads();

    int nT = klen / GK;
    int buf = 0;
    for (int it = 0; it < nT; it++) {
        if (it + 1 < nT) {
            int ko = (it + 1) * GK;
            ra0 = *(const float4*)(Abase0 + ko);
            ra1 = *(const float4*)(Abase1 + ko);
            rw0 = wok ? *(const float4*)(Wbase0 + (size_t)ko * N)
                      : make_float4(0.f, 0.f, 0.f, 0.f);
            rw1 = wok ? *(const float4*)(Wbase1 + (size_t)ko * N)
                      : make_float4(0.f, 0.f, 0.f, 0.f);
        }
#pragma unroll
        for (int kk = 0; kk < GK; kk++) {
            F2U a0, a1, a2, a3, b0, b1;
            a0.f = As2[buf][kk][ty * 4 + 0];
            a1.f = As2[buf][kk][ty * 4 + 1];
            a2.f = As2[buf][kk][ty * 4 + 2];
            a3.f = As2[buf][kk][ty * 4 + 3];
            b0.f = *(const float2*)&Ws[buf][kk][tx * 4];
            b1.f = *(const float2*)&Ws[buf][kk][tx * 4 + 2];
            acc[0][0] = fma2(a0.u, b0.u, acc[0][0]);
            acc[0][1] = fma2(a0.u, b1.u, acc[0][1]);
            acc[1][0] = fma2(a1.u, b0.u, acc[1][0]);
            acc[1][1] = fma2(a1.u, b1.u, acc[1][1]);
            acc[2][0] = fma2(a2.u, b0.u, acc[2][0]);
            acc[2][1] = fma2(a2.u, b1.u, acc[2][1]);
            acc[3][0] = fma2(a3.u, b0.u, acc[3][0]);
            acc[3][1] = fma2(a3.u, b1.u, acc[3][1]);
        }
        if (it + 1 < nT) {
            int nb = buf ^ 1;
            As2[nb][akq * 4 + 0][arow] = make_float2(ra0.x, ra0.x);
            As2[nb][akq * 4 + 1][arow] = make_float2(ra0.y, ra0.y);
            As2[nb][akq * 4 + 2][arow] = make_float2(ra0.z, ra0.z);
            As2[nb][akq * 4 + 3][arow] = make_float2(ra0.w, ra0.w);
            As2[nb][akq * 4 + 0][arow + 32] = make_float2(ra1.x, ra1.x);
            As2[nb][akq * 4 + 1][arow + 32] = make_float2(ra1.y, ra1.y);
            As2[nb][akq * 4 + 2][arow + 32] = make_float2(ra1.z, ra1.z);
            As2[nb][akq * 4 + 3][arow + 32] = make_float2(ra1.w, ra1.w);
            *(float4*)&Ws[nb][wkk][wnq * 4] = rw0;
            *(float4*)&Ws[nb][16 + wkk][wnq * 4] = rw1;
            __syncthreads();
        }
        buf ^= 1;
    }

    if (ksplit > 1) {
        float* P = part + (size_t)(gi * ksplit + kz) * M * N;
#pragma unroll
        for (int i = 0; i < 4; i++) {
            int row = m0 + ty * 4 + i;
#pragma unroll
            for (int jp = 0; jp < 2; jp++) {
                int col = n0 + tx * 4 + jp * 2;
                F2U t; t.u = acc[i][jp];
                if (col < N)     P[(size_t)row * N + col] = t.f.x;
                if (col + 1 < N) P[(size_t)row * N + col + 1] = t.f.y;
            }
        }
    } else {
#pragma unroll
        for (int i = 0; i < 4; i++) {
            int row = m0 + ty * 4 + i;
#pragma unroll
            for (int jp = 0; jp < 2; jp++) {
                int col = n0 + tx * 4 + jp * 2;
                F2U t; t.u = acc[i][jp];
                if (col < N) {
                    float v = t.f.x + g.bias[col];
                    if (mode == 1) v += SIGMA * g.eps[(size_t)row * N + col];
                    if (mode == 2) v = fmaxf(v, 0.0f);
                    g.C[(size_t)row * N + col] = v;
                }
                if (col + 1 < N) {
                    float v = t.f.y + g.bias[col + 1];
                    if (mode == 1) v += SIGMA * g.eps[(size_t)row * N + col + 1];
                    if (mode == 2) v = fmaxf(v, 0.0f);
                    g.C[(size_t)row * N + col + 1] = v;
                }
            }
        }
    }
}

// ---------------- big-N GEMM (Wout): 128x64 tile, 8x4 per thread ----------
#define BBK 16

__global__ __launch_bounds__(256, 2)
void gemm_big_kernel(const float* __restrict__ A, const float* __restrict__ W,
                     const float* __restrict__ bias, float* __restrict__ C,
                     int N, int K) {
    __shared__ float  As[2][BBK][128];    // transposed, natural: 16 KB
    __shared__ float2 Bs[2][BBK][64];     // duplicated {b,b}:    16 KB
    int tid = threadIdx.x;
    int tx = tid & 15;          // 16 col groups x 4 cols
    int ty = tid >> 4;          // 16 row groups x 8 rows
    int n0 = blockIdx.x * 64;

    unsigned long long acc[4][4];   // [row-pair p][col j]
#pragma unroll
    for (int p = 0; p < 4; p++)
#pragma unroll
        for (int j = 0; j < 4; j++) acc[p][j] = 0ULL;

    int arow = tid >> 1, akb = (tid & 1) * 8;        // A: 128 rows x 16 k
    int brow = tid >> 4, bcb = (tid & 15) * 4;       // B: 16 k x 64 cols

    const float* Abase = &A[(size_t)arow * K + akb];
    float4 ra0, ra1;
    float rb[4];
    int bc[4];
    bool bok[4];
#pragma unroll
    for (int i = 0; i < 4; i++) { bc[i] = n0 + bcb + i; bok[i] = (bc[i] < N); }

    // prologue
    ra0 = *(const float4*)(Abase);
    ra1 = *(const float4*)(Abase + 4);
#pragma unroll
    for (int i = 0; i < 4; i++)
        rb[i] = bok[i] ? W[(size_t)brow * N + bc[i]] : 0.0f;
    {
        As[0][akb + 0][arow] = ra0.x;  As[0][akb + 1][arow] = ra0.y;
        As[0][akb + 2][arow] = ra0.z;  As[0][akb + 3][arow] = ra0.w;
        As[0][akb + 4][arow] = ra1.x;  As[0][akb + 5][arow] = ra1.y;
        As[0][akb + 6][arow] = ra1.z;  As[0][akb + 7][arow] = ra1.w;
#pragma unroll
        for (int i = 0; i < 4; i++) Bs[0][brow][bcb + i] = make_float2(rb[i], rb[i]);
    }
    __syncthreads();

    int nT = K / BBK;
    int buf = 0;
    for (int it = 0; it < nT; it++) {
        if (it + 1 < nT) {
            int ko = (it + 1) * BBK;
            ra0 = *(const float4*)(Abase + ko);
            ra1 = *(const float4*)(Abase + ko + 4);
#pragma unroll
            for (int i = 0; i < 4; i++)
                rb[i] = bok[i] ? W[(size_t)(ko + brow) * N + bc[i]] : 0.0f;
        }
#pragma unroll
        for (int kk = 0; kk < BBK; kk++) {
            F2U ar[4], br[4];
#pragma unroll
            for (int p = 0; p < 4; p++)
                ar[p].f = *(const float2*)&As[buf][kk][ty * 8 + p * 2];
#pragma unroll
            for (int j = 0; j < 4; j++)
                br[j].f = Bs[buf][kk][tx * 4 + j];
#pragma unroll
            for (int p = 0; p < 4; p++)
#pragma unroll
                for (int j = 0; j < 4; j++)
                    acc[p][j] = fma2(ar[p].u, br[j].u, acc[p][j]);
        }
        if (it + 1 < nT) {
            int nb = buf ^ 1;
            As[nb][akb + 0][arow] = ra0.x;  As[nb][akb + 1][arow] = ra0.y;
            As[nb][akb + 2][arow] = ra0.z;  As[nb][akb + 3][arow] = ra0.w;
            As[nb][akb + 4][arow] = ra1.x;  As[nb][akb + 5][arow] = ra1.y;
            As[nb][akb + 6][arow] = ra1.z;  As[nb][akb + 7][arow] = ra1.w;
#pragma unroll
            for (int i = 0; i < 4; i++) Bs[nb][brow][bcb + i] = make_float2(rb[i], rb[i]);
            __syncthreads();
        }
        buf ^= 1;
    }

#pragma unroll
    for (int p = 0; p < 4; p++) {
        int row0 = ty * 8 + p * 2;
#pragma unroll
        for (int j = 0; j < 4; j++) {
            int col = n0 + tx * 4 + j;
            if (col < N) {
                F2U t; t.u = acc[p][j];
                float bsv = bias[col];
                C[(size_t)row0 * N + col]       = t.f.x + bsv;
                C[(size_t)(row0 + 1) * N + col] = t.f.y + bsv;
            }
        }
    }
}

// ---------------- epilogue: sum partials + bias (+eps / relu) ----------------
struct EArgs { const float* bias; const float* eps; float* C; };

__global__ __launch_bounds__(256)
void epi_simple_kernel(EArgs e0, EArgs e1, EArgs e2, int N, int MN,
                       int ksplit, int mode, const float* part) {
    int gi = blockIdx.y;
    EArgs e = (gi == 0) ? e0 : (gi == 1) ? e1 : e2;
    int idx = blockIdx.x * 256 + threadIdx.x;
    if (idx >= MN) return;
    int col = idx % N;
    float v = e.bias[col];
    const float* P = part + (size_t)gi * ksplit * MN + idx;
    for (int kz = 0; kz < ksplit; kz++) v += P[(size_t)kz * MN];
    if (mode == 1) v += SIGMA * e.eps[idx];
    if (mode == 2) v = fmaxf(v, 0.0f);
    e.C[idx] = v;
}

// ---------------- epilogue with fused LayerNorm (N = DD = 512) ----------------
__global__ __launch_bounds__(256)
void epi_ln_kernel(const float* part, int ksplit,
                   const float* __restrict__ bias, const float* __restrict__ eps,
                   const float* __restrict__ add, const float* __restrict__ gam,
                   const float* __restrict__ bet, float* __restrict__ mid,
                   float* __restrict__ out) {
    int row = blockIdx.x;
    int tid = threadIdx.x;
    __shared__ float sh[8];
    __shared__ float s_mu, s_inv;

    int c0 = tid, c1 = tid + 256;
    float v0 = bias[c0], v1 = bias[c1];
    for (int kz = 0; kz < ksplit; kz++) {
        const float* P = part + (size_t)kz * NROW * DD + (size_t)row * DD;
        v0 += P[c0];
        v1 += P[c1];
    }
    if (eps) {
        v0 += SIGMA * eps[(size_t)row * DD + c0];
        v1 += SIGMA * eps[(size_t)row * DD + c1];
    }
    if (mid) {
        mid[(size_t)row * DD + c0] = v0;
        mid[(size_t)row * DD + c1] = v1;
    }
    float x0 = v0 + add[(size_t)row * DD + c0];
    float x1 = v1 + add[(size_t)row * DD + c1];

    float s = x0 + x1;
    float sq = x0 * x0 + x1 * x1;
#pragma unroll
    for (int o = 16; o; o >>= 1) {
        s  += __shfl_xor_sync(~0u, s, o);
        sq += __shfl_xor_sync(~0u, sq, o);
    }
    if ((tid & 31) == 0) sh[tid >> 5] = s;
    __syncthreads();
    if (tid == 0) {
        float t = 0;
        for (int i = 0; i < 8; i++) t += sh[i];
        s_mu = t / DD;
    }
    __syncthreads();
    if ((tid & 31) == 0) sh[tid >> 5] = sq;
    __syncthreads();
    if (tid == 0) {
        float t = 0;
        for (int i = 0; i < 8; i++) t += sh[i];
        float var = t / DD - s_mu * s_mu;
        s_inv = rsqrtf(var + LN_EPS);
    }
    __syncthreads();
    float mu = s_mu, inv = s_inv;
    out[(size_t)row * DD + c0] = (x0 - mu) * inv * gam[c0] + bet[c0];
    out[(size_t)row * DD + c1] = (x1 - mu) * inv * gam[c1] + bet[c1];
}

// ---------------- attention ----------------
__global__ __launch_bounds__(256)
void attn_kernel(const float* __restrict__ Kin, const float* __restrict__ Vin,
                 float* __restrict__ attnw, const int* __restrict__ tptr) {
    int t = *tptr;
    int tlen = t + 1;
    if (tlen > SS) tlen = SS;
    int bp = blockIdx.x;
    int tid = threadIdx.x;

    __shared__ float qs[DD];
    __shared__ float sc[HH][SS + 8];

    qs[tid] = g_q[bp * DD + tid];
    qs[tid + 256] = g_q[bp * DD + 256 + tid];
    __syncthreads();

    for (int idx = tid; idx < HH * tlen; idx += 256) {
        int h = idx / tlen;
        int s = idx - h * tlen;
        const float* kr = (s == t) ? &g_k[bp * DD]
                                   : &Kin[((size_t)bp * SS + s) * DD];
        const float4* k4 = (const float4*)(kr + h * DEPTH);
        const float4* q4 = (const float4*)(qs + h * DEPTH);
        float acc = 0.0f;
#pragma unroll
        for (int i = 0; i < DEPTH / 4; i++) {
            float4 kv = k4[i], qv = q4[i];
            acc += kv.x * qv.x + kv.y * qv.y + kv.z * qv.z + kv.w * qv.w;
        }
        sc[h][s] = acc * 0.125f;
    }
    __syncthreads();

    int wid = tid >> 5, lane = tid & 31;
    {
        float mx = -1e30f;
        for (int s = lane; s < tlen; s += 32) mx = fmaxf(mx, sc[wid][s]);
#pragma unroll
        for (int o = 16; o; o >>= 1) mx = fmaxf(mx, __shfl_xor_sync(~0u, mx, o));
        float sum = 0.0f;
        for (int s = lane; s < tlen; s += 32) {
            float e = __expf(sc[wid][s] - mx);
            sc[wid][s] = e;
            sum += e;
        }
#pragma unroll
        for (int o = 16; o; o >>= 1) sum += __shfl_xor_sync(~0u, sum, o);
        float r = 1.0f / sum;
        for (int s = lane; s < tlen; s += 32) sc[wid][s] *= r;
    }
    __syncthreads();

    for (int s = tid; s < SS; s += 256) {
        float v = 0.0f;
        if (s < tlen) {
#pragma unroll
            for (int h = 0; h < HH; h++) v += sc[h][s];
            v *= (1.0f / HH);
        }
        attnw[(size_t)bp * SS + s] = v;
    }

    int d0 = tid, d1 = tid + 256;
    int h0 = d0 >> 6, h1 = d1 >> 6;
    float acc0 = 0.0f, acc1 = 0.0f;
#pragma unroll 4
    for (int s = 0; s < tlen; s++) {
        const float* vr = (s == t) ? &g_v[bp * DD]
                                   : &Vin[((size_t)bp * SS + s) * DD];
        acc0 += sc[h0][s] * vr[d0];
        acc1 += sc[h1][s] * vr[d1];
    }
    g_zattn[bp * DD + d0] = acc0;
    g_zattn[bp * DD + d1] = acc1;
}

// ---------------- per-row softmax stats over VOC ----------------
__global__ __launch_bounds__(256)
void rowsoftmax_kernel(const int* __restrict__ x, float* __restrict__ wnew) {
    int row = blockIdx.x;
    const float* pr = g_pred + (size_t)row * VOC;
    int tid = threadIdx.x;
    __shared__ float sh[8];
    __shared__ float s_mx;

    float mx = -1e30f;
    for (int c = tid; c < VOC; c += 256) mx = fmaxf(mx, pr[c]);
#pragma unroll
    for (int o = 16; o; o >>= 1) mx = fmaxf(mx, __shfl_xor_sync(~0u, mx, o));
    if ((tid & 31) == 0) sh[tid >> 5] = mx;
    __syncthreads();
    if (tid == 0) {
        float m = sh[0];
        for (int i = 1; i < 8; i++) m = fmaxf(m, sh[i]);
        s_mx = m;
    }
    __syncthreads();
    mx = s_mx;
    float sum = 0.0f;
    for (int c = tid; c < VOC; c += 256) sum += __expf(pr[c] - mx);
#pragma unroll
    for (int o = 16; o; o >>= 1) sum += __shfl_xor_sync(~0u, sum, o);
    __syncthreads();
    if ((tid & 31) == 0) sh[tid >> 5] = sum;
    __syncthreads();
    if (tid == 0) {
        float sm = 0;
        for (int i = 0; i < 8; i++) sm += sh[i];
        g_rowmax[row] = mx;
        g_rowrsum[row] = 1.0f / sm;
        int b = row >> 4;
        float w = __expf(pr[x[b]] - mx) / sm;
        g_wsq[row] = w;
        g_lw[row] = logf(w + 1e-10f);
        wnew[row] = w;
    }
}

// ---- shared helpers: gumbel-argmax i_t and argmax over w (redundant) -------
__device__ __forceinline__ int compute_it(int b, int p,
                                          const float* __restrict__ gumbel) {
    const float* lw = &g_lw[b * PP];
    const float* gr = &gumbel[(size_t)(b * PP + p) * PP];
    float best = -1e38f;
    int arg = 0;
#pragma unroll
    for (int j = 0; j < PP; j++) {
        float v = lw[j] + gr[j];
        if (v > best) { best = v; arg = j; }
    }
    return arg;
}

__device__ __forceinline__ int compute_argmax_w(int b) {
    float bw = g_wsq[b * PP];
    int a = 0;
#pragma unroll
    for (int j = 1; j < PP; j++) {
        float w = g_wsq[b * PP + j];
        if (w > bw) { bw = w; a = j; }
    }
    return a;
}

// ---------------- final fused kernel: resample + misc + vocab reductions ----
#define NRES_BLK (NROW * SS / 2)          // 32768
#define NMISC_BLK 256
#define NVOC_PER_B 40                     // ceil(10000/256)
#define NVOC_BLK (NVOC_PER_B * BB)        // 320

__global__ __launch_bounds__(256)
void final_kernel(const float* __restrict__ Kin, const float* __restrict__ gumbel,
                  const int* __restrict__ I, const float* __restrict__ r,
                  const float* __restrict__ epsz, const int* __restrict__ tptr,
                  float* __restrict__ out) {
    int t = *tptr;
    int bid = blockIdx.x;
    int tid = threadIdx.x;
    __shared__ int s_i[4];

    if (bid < NRES_BLK) {
        // ---- K/Vs resample: 2 rows per block (row = bp*512 + s) ----
        int half = tid >> 7;
        int rid = bid * 2 + half;
        int d4 = tid & 127;
        int s = rid & 511;
        int bp = rid >> 9;
        int b = bp >> 4;
        if ((tid & 127) == 0) {
            int i1 = compute_it(b, bp & 15, gumbel);
            s_i[half * 2]     = i1;
            s_i[half * 2 + 1] = compute_it(b, i1, gumbel);
        }
        __syncthreads();
        size_t dst = (size_t)rid * DD + d4 * 4;
        if (s > t) {
            float4 v = __ldg(&((const float4*)&Kin[((size_t)bp * SS + s) * DD])[d4]);
            __stcs((float4*)&out[OFF_K + dst], v);
            __stcs((float4*)&out[OFF_V + dst], v);
        } else {
            int i1 = s_i[half * 2], i2 = s_i[half * 2 + 1];
            const float* sk = (s == t) ? &g_k[(b * PP + i1) * DD]
                                       : &Kin[(((size_t)(b * PP + i1)) * SS + s) * DD];
            const float* sv = (s == t) ? &g_k[(b * PP + i2) * DD]
                                       : &Kin[(((size_t)(b * PP + i2)) * SS + s) * DD];
            __stcs((float4*)&out[OFF_K + dst], ((const float4*)sk)[d4]);
            __stcs((float4*)&out[OFF_V + dst], ((const float4*)sv)[d4]);
        }
    } else if (bid < NRES_BLK + NMISC_BLK) {
        // ---- misc copies / gathers: 256 idx per block, single row ----
        int mb = bid - NRES_BLK;
        int idx = mb * 256 + tid;
        int row = idx >> 9, d = idx & 511;
        int b = row >> 4;
        if (tid == 0) s_i[0] = compute_it(b, row & 15, gumbel);
        __syncthreads();
        int i1 = s_i[0];
        out[OFF_R4 + idx] = r[idx];
        out[OFF_EPSZ + idx] = epsz[idx];
        out[OFF_Z + idx] = g_z[(b * PP + i1) * DD + d];
        int val;
        if (d < t)       val = I[(b * PP + i1) * SS + d];
        else if (d == t) val = i1;
        else             val = I[idx];
        out[OFF_INEW + idx] = (float)val;
    } else {
        // ---- vocab reductions over particles ----
        int vb = bid - NRES_BLK - NMISC_BLK;
        int b = vb / NVOC_PER_B;
        int cb = vb - b * NVOC_PER_B;
        int c = cb * 256 + tid;
        if (c >= VOC) return;
        int am = compute_argmax_w(b);
        float sp = 0.0f, ss = 0.0f, mp = 0.0f;
#pragma unroll
        for (int p = 0; p < PP; p++) {
            int row = b * PP + p;
            float v = g_pred[(size_t)row * VOC + c];
            sp += v;
            ss += __expf(v - g_rowmax[row]) * g_rowrsum[row];
            if (p == am) mp = v;
        }
        __stcs(&out[OFF_GAVG + (size_t)b * VOC + c], sp * (1.0f / PP));
        __stcs(&out[OFF_AVGS + (size_t)b * VOC + c], ss * (1.0f / PP));
        __stcs(&out[OFF_MAXP + (size_t)b * VOC + c], mp);
    }
}

// ---------------- launch ----------------
extern "C" void kernel_launch(void* const* d_in, const int* in_sizes, int n_in,
                              void* d_out, int out_size) {
    (void)in_sizes; (void)n_in; (void)out_size;
    const float* r      = (const float*)d_in[0];
    const int*   x      = (const int*)d_in[1];
    const float* Kin    = (const float*)d_in[2];
    const float* Vin    = (const float*)d_in[3];
    const int*   I      = (const int*)d_in[5];
    const int*   tptr   = (const int*)d_in[6];
    const float* eps_q  = (const float*)d_in[7];
    const float* eps_k  = (const float*)d_in[8];
    const float* eps_v  = (const float*)d_in[9];
    const float* eps_z  = (const float*)d_in[10];
    const float* gumbel = (const float*)d_in[11];
    const float* Wq = (const float*)d_in[12];
    const float* bq = (const float*)d_in[13];
    const float* Wk = (const float*)d_in[14];
    const float* bk = (const float*)d_in[15];
    const float* Wv = (const float*)d_in[16];
    const float* bv = (const float*)d_in[17];
    const float* Wo = (const float*)d_in[18];
    const float* bo = (const float*)d_in[19];
    const float* ln1_g = (const float*)d_in[20];
    const float* ln1_b = (const float*)d_in[21];
    const float* ln3_g = (const float*)d_in[22];
    const float* ln3_b = (const float*)d_in[23];
    const float* W1 = (const float*)d_in[24];
    const float* b1 = (const float*)d_in[25];
    const float* W2 = (const float*)d_in[26];
    const float* b2 = (const float*)d_in[27];
    const float* Wout = (const float*)d_in[28];
    const float* bout = (const float*)d_in[29];
    float* out = (float*)d_out;

    float *p_q, *p_k, *p_v, *p_zattn, *p_z, *p_out1, *p_h, *p_rr, *p_pred, *p_part;
    cudaGetSymbolAddress((void**)&p_q, g_q);
    cudaGetSymbolAddress((void**)&p_k, g_k);
    cudaGetSymbolAddress((void**)&p_v, g_v);
    cudaGetSymbolAddress((void**)&p_zattn, g_zattn);
    cudaGetSymbolAddress((void**)&p_z, g_z);
    cudaGetSymbolAddress((void**)&p_out1, g_out1);
    cudaGetSymbolAddress((void**)&p_h, g_h);
    cudaGetSymbolAddress((void**)&p_rr, g_rr);
    cudaGetSymbolAddress((void**)&p_pred, g_pred);
    cudaGetSymbolAddress((void**)&p_part, g_part);

    GArgs gz0{nullptr, nullptr, nullptr, nullptr, nullptr};

    // 1. q,k,v projections: split-K 8 -> partials, then epilogue (+bias +eps)
    {
        GArgs gq{r, Wq, bq, eps_q, p_q};
        GArgs gk{r, Wk, bk, eps_k, p_k};
        GArgs gv{r, Wv, bv, eps_v, p_v};
        gemm2_kernel<<<dim3(DD / GN, NROW / GM, 3 * 8), 256>>>(
            gq, gk, gv, NROW, DD, DD, 8, DD / 8, 1, p_part);
        EArgs eq{bq, eps_q, p_q};
        EArgs ek{bk, eps_k, p_k};
        EArgs ev{bv, eps_v, p_v};
        epi_simple_kernel<<<dim3(NROW * DD / 256, 3), 256>>>(
            eq, ek, ev, DD, NROW * DD, 8, 1, p_part);
    }
    // 2. attention
    attn_kernel<<<NROW, 256>>>(Kin, Vin, out + OFF_ATTNW, tptr);
    // 3. z = zattn @ Wo (+bo +eps_z), split-K 8 (klen 64 -> pipelined), +LN1
    {
        GArgs gw{p_zattn, Wo, bo, eps_z, p_z};
        gemm2_kernel<<<dim3(DD / GN, NROW / GM, 8), 256>>>(
            gw, gz0, gz0, NROW, DD, DD, 8, DD / 8, 0, p_part);
        epi_ln_kernel<<<NROW, 256>>>(p_part, 8, bo, eps_z, r, ln1_g, ln1_b,
                                     p_z, p_out1);
    }
    // 4. h = relu(out1 @ W1 + b1), split-K 4
    {
        GArgs gw{p_out1, W1, b1, nullptr, p_h};
        gemm2_kernel<<<dim3(DFF / GN, NROW / GM, 4), 256>>>(
            gw, gz0, gz0, NROW, DFF, DD, 4, DD / 4, 0, p_part);
        EArgs ef{b1, nullptr, p_h};
        epi_simple_kernel<<<dim3(NROW * DFF / 256, 1), 256>>>(
            ef, ef, ef, DFF, NROW * DFF, 4, 2, p_part);
    }
    // 5. f = h @ W2 + b2, split-K 16, fused epilogue+LN3 -> g_rr
    {
        GArgs gw{p_h, W2, b2, nullptr, p_rr};
        gemm2_kernel<<<dim3(DD / GN, NROW / GM, 16), 256>>>(
            gw, gz0, gz0, NROW, DD, DFF, 16, DFF / 16, 0, p_part);
        epi_ln_kernel<<<NROW, 256>>>(p_part, 16, b2, nullptr, p_out1,
                                     ln3_g, ln3_b, nullptr, p_rr);
    }
    // 6. predictions = r_ @ Wout + bout (dedicated big-N kernel, grid 157)
    gemm_big_kernel<<<(VOC + 63) / 64, 256>>>(p_rr, Wout, bout, p_pred, VOC, DD);
    // 7. softmax stats + w_sq + log-weights
    rowsoftmax_kernel<<<NROW, 256>>>(x, out + OFF_WNEW);
    // 8. fused: K/Vs resample + misc gathers + vocab reductions
    final_kernel<<<NRES_BLK + NMISC_BLK + NVOC_BLK, 256>>>(
        Kin, gumbel, I, r, eps_z, tptr, out);
}

// round 10
// speedup vs baseline: 1.4025x; 1.4025x over previous
#include <cuda_runtime.h>
#include <cuda_bf16.h>
#include <cstdint>
#include <cstdio>

// Problem constants
#define BB 8
#define PP 16
#define SS 512
#define DD 512
#define HH 8
#define DEPTH 64
#define DFF 2048
#define VOC 10000
#define NROW 128              // B*P
#define SIGMA 0.1f
#define LN_EPS 1e-6f

// Output offsets (float elements)
static const size_t OFF_R4    = 0;
static const size_t OFF_Z     = 65536;
static const size_t OFF_AVGS  = 131072;
static const size_t OFF_GAVG  = 211072;
static const size_t OFF_MAXP  = 291072;
static const size_t OFF_EPSZ  = 371072;
static const size_t OFF_ATTNW = 436608;
static const size_t OFF_K     = 502144;
static const size_t OFF_V     = 502144ULL + 33554432ULL;
static const size_t OFF_WNEW  = 67611008ULL;
static const size_t OFF_INEW  = 67611136ULL;

// ---------------- device scratch ----------------
__device__ float g_q[NROW * DD];
__device__ float g_k[NROW * DD];
__device__ float g_v[NROW * DD];
__device__ float g_zattn[NROW * DD];
__device__ float g_z[NROW * DD];
__device__ float g_out1[NROW * DD];
__device__ float g_h[NROW * DFF];
__device__ float g_rr[NROW * DD];
__device__ float g_pred[NROW * VOC];
__device__ float g_part[3 * 4 * NROW * DD * 4];   // partial buffer
__device__ float g_rowmax[NROW];
__device__ float g_rowrsum[NROW];
__device__ float g_wsq[NROW];
__device__ int   g_it[NROW];
__device__ int   g_argmax[BB];

// ---------------- packed f32x2 helpers ----------------
union F2U { float2 f; unsigned long long u; };

__device__ __forceinline__ unsigned long long fma2(unsigned long long a,
                                                   unsigned long long b,
                                                   unsigned long long c) {
    unsigned long long d;
    asm("fma.rn.f32x2 %0, %1, %2, %3;" : "=l"(d) : "l"(a), "l"(b), "l"(c));
    return d;
}

// ---------------- GEMM v3: double-buffered split-K (small GEMMs) ----------
struct GArgs {
    const float* A;
    const float* W;
    const float* bias;
    const float* eps;
    float* C;
};

#define GM 64
#define GN 64
#define GK 32

__global__ __launch_bounds__(256, 2)
void gemm2_kernel(GArgs g0, GArgs g1, GArgs g2, int M, int N, int K,
                  int ksplit, int klen, int mode, float* part) {
    int z = blockIdx.z;
    int gi = z / ksplit, kz = z - gi * ksplit;
    GArgs g = (gi == 0) ? g0 : (gi == 1) ? g1 : g2;

    __shared__ float2 As2[2][GK][GM];   // duplicated {a,a}; 32 KB
    __shared__ float  Ws[2][GK][GN];    // 16 KB  (total 48 KB)

    int tid = threadIdx.x;
    int tx = tid & 15, ty = tid >> 4;
    int m0 = blockIdx.y * GM;
    int n0 = blockIdx.x * GN;
    int kbase = kz * klen;

    unsigned long long acc[4][2];
#pragma unroll
    for (int i = 0; i < 4; i++) { acc[i][0] = 0ULL; acc[i][1] = 0ULL; }

    int arow = tid >> 3, akq = tid & 7;
    int wkk = tid >> 4, wnq = tid & 15;

    const float* Abase0 = &g.A[(size_t)(m0 + arow) * K + kbase + akq * 4];
    const float* Abase1 = &g.A[(size_t)(m0 + 32 + arow) * K + kbase + akq * 4];
    int ncol = n0 + wnq * 4;
    bool wok = (ncol < N);
    const float* Wbase0 = &g.W[(size_t)(kbase + wkk) * N + ncol];
    const float* Wbase1 = &g.W[(size_t)(kbase + 16 + wkk) * N + ncol];

    float4 ra0, ra1, rw0, rw1;

    ra0 = *(const float4*)(Abase0);
    ra1 = *(const float4*)(Abase1);
    rw0 = wok ? *(const float4*)(Wbase0) : make_float4(0.f, 0.f, 0.f, 0.f);
    rw1 = wok ? *(const float4*)(Wbase1) : make_float4(0.f, 0.f, 0.f, 0.f);
    {
        As2[0][akq * 4 + 0][arow] = make_float2(ra0.x, ra0.x);
        As2[0][akq * 4 + 1][arow] = make_float2(ra0.y, ra0.y);
        As2[0][akq * 4 + 2][arow] = make_float2(ra0.z, ra0.z);
        As2[0][akq * 4 + 3][arow] = make_float2(ra0.w, ra0.w);
        As2[0][akq * 4 + 0][arow + 32] = make_float2(ra1.x, ra1.x);
        As2[0][akq * 4 + 1][arow + 32] = make_float2(ra1.y, ra1.y);
        As2[0][akq * 4 + 2][arow + 32] = make_float2(ra1.z, ra1.z);
        As2[0][akq * 4 + 3][arow + 32] = make_float2(ra1.w, ra1.w);
        *(float4*)&Ws[0][wkk][wnq * 4] = rw0;
        *(float4*)&Ws[0][16 + wkk][wnq * 4] = rw1;
    }
    __syncthreads();

    int nT = klen / GK;
    int buf = 0;
    for (int it = 0; it < nT; it++) {
        if (it + 1 < nT) {
            int ko = (it + 1) * GK;
            ra0 = *(const float4*)(Abase0 + ko);
            ra1 = *(const float4*)(Abase1 + ko);
            rw0 = wok ? *(const float4*)(Wbase0 + (size_t)ko * N)
                      : make_float4(0.f, 0.f, 0.f, 0.f);
            rw1 = wok ? *(const float4*)(Wbase1 + (size_t)ko * N)
                      : make_float4(0.f, 0.f, 0.f, 0.f);
        }
#pragma unroll
        for (int kk = 0; kk < GK; kk++) {
            F2U a0, a1, a2, a3, b0, b1;
            a0.f = As2[buf][kk][ty * 4 + 0];
            a1.f = As2[buf][kk][ty * 4 + 1];
            a2.f = As2[buf][kk][ty * 4 + 2];
            a3.f = As2[buf][kk][ty * 4 + 3];
            b0.f = *(const float2*)&Ws[buf][kk][tx * 4];
            b1.f = *(const float2*)&Ws[buf][kk][tx * 4 + 2];
            acc[0][0] = fma2(a0.u, b0.u, acc[0][0]);
            acc[0][1] = fma2(a0.u, b1.u, acc[0][1]);
            acc[1][0] = fma2(a1.u, b0.u, acc[1][0]);
            acc[1][1] = fma2(a1.u, b1.u, acc[1][1]);
            acc[2][0] = fma2(a2.u, b0.u, acc[2][0]);
            acc[2][1] = fma2(a2.u, b1.u, acc[2][1]);
            acc[3][0] = fma2(a3.u, b0.u, acc[3][0]);
            acc[3][1] = fma2(a3.u, b1.u, acc[3][1]);
        }
        if (it + 1 < nT) {
            int nb = buf ^ 1;
            As2[nb][akq * 4 + 0][arow] = make_float2(ra0.x, ra0.x);
            As2[nb][akq * 4 + 1][arow] = make_float2(ra0.y, ra0.y);
            As2[nb][akq * 4 + 2][arow] = make_float2(ra0.z, ra0.z);
            As2[nb][akq * 4 + 3][arow] = make_float2(ra0.w, ra0.w);
            As2[nb][akq * 4 + 0][arow + 32] = make_float2(ra1.x, ra1.x);
            As2[nb][akq * 4 + 1][arow + 32] = make_float2(ra1.y, ra1.y);
            As2[nb][akq * 4 + 2][arow + 32] = make_float2(ra1.z, ra1.z);
            As2[nb][akq * 4 + 3][arow + 32] = make_float2(ra1.w, ra1.w);
            *(float4*)&Ws[nb][wkk][wnq * 4] = rw0;
            *(float4*)&Ws[nb][16 + wkk][wnq * 4] = rw1;
            __syncthreads();
        }
        buf ^= 1;
    }

    if (ksplit > 1) {
        float* P = part + (size_t)(gi * ksplit + kz) * M * N;
#pragma unroll
        for (int i = 0; i < 4; i++) {
            int row = m0 + ty * 4 + i;
#pragma unroll
            for (int jp = 0; jp < 2; jp++) {
                int col = n0 + tx * 4 + jp * 2;
                F2U t; t.u = acc[i][jp];
                if (col < N)     P[(size_t)row * N + col] = t.f.x;
                if (col + 1 < N) P[(size_t)row * N + col + 1] = t.f.y;
            }
        }
    } else {
#pragma unroll
        for (int i = 0; i < 4; i++) {
            int row = m0 + ty * 4 + i;
#pragma unroll
            for (int jp = 0; jp < 2; jp++) {
                int col = n0 + tx * 4 + jp * 2;
                F2U t; t.u = acc[i][jp];
                if (col < N) {
                    float v = t.f.x + g.bias[col];
                    if (mode == 1) v += SIGMA * g.eps[(size_t)row * N + col];
                    if (mode == 2) v = fmaxf(v, 0.0f);
                    g.C[(size_t)row * N + col] = v;
                }
                if (col + 1 < N) {
                    float v = t.f.y + g.bias[col + 1];
                    if (mode == 1) v += SIGMA * g.eps[(size_t)row * N + col + 1];
                    if (mode == 2) v = fmaxf(v, 0.0f);
                    g.C[(size_t)row * N + col + 1] = v;
                }
            }
        }
    }
}

// ---------------- big-N GEMM (Wout): 128x64 tile, 8x4 per thread ----------
#define BBK 16

__global__ __launch_bounds__(256, 2)
void gemm_big_kernel(const float* __restrict__ A, const float* __restrict__ W,
                     const float* __restrict__ bias, float* __restrict__ C,
                     int N, int K) {
    __shared__ float  As[2][BBK][128];    // transposed, natural: 16 KB
    __shared__ float2 Bs[2][BBK][64];     // duplicated {b,b}:    16 KB
    int tid = threadIdx.x;
    int tx = tid & 15;          // 16 col groups x 4 cols
    int ty = tid >> 4;          // 16 row groups x 8 rows
    int n0 = blockIdx.x * 64;

    unsigned long long acc[4][4];   // [row-pair p][col j]
#pragma unroll
    for (int p = 0; p < 4; p++)
#pragma unroll
        for (int j = 0; j < 4; j++) acc[p][j] = 0ULL;

    int arow = tid >> 1, akb = (tid & 1) * 8;        // A: 128 rows x 16 k
    int brow = tid >> 4, bcb = (tid & 15) * 4;       // B: 16 k x 64 cols

    const float* Abase = &A[(size_t)arow * K + akb];
    float4 ra0, ra1;
    float rb[4];
    int bc[4];
    bool bok[4];
#pragma unroll
    for (int i = 0; i < 4; i++) { bc[i] = n0 + bcb + i; bok[i] = (bc[i] < N); }

    ra0 = *(const float4*)(Abase);
    ra1 = *(const float4*)(Abase + 4);
#pragma unroll
    for (int i = 0; i < 4; i++)
        rb[i] = bok[i] ? W[(size_t)brow * N + bc[i]] : 0.0f;
    {
        As[0][akb + 0][arow] = ra0.x;  As[0][akb + 1][arow] = ra0.y;
        As[0][akb + 2][arow] = ra0.z;  As[0][akb + 3][arow] = ra0.w;
        As[0][akb + 4][arow] = ra1.x;  As[0][akb + 5][arow] = ra1.y;
        As[0][akb + 6][arow] = ra1.z;  As[0][akb + 7][arow] = ra1.w;
#pragma unroll
        for (int i = 0; i < 4; i++) Bs[0][brow][bcb + i] = make_float2(rb[i], rb[i]);
    }
    __syncthreads();

    int nT = K / BBK;
    int buf = 0;
    for (int it = 0; it < nT; it++) {
        if (it + 1 < nT) {
            int ko = (it + 1) * BBK;
            ra0 = *(const float4*)(Abase + ko);
            ra1 = *(const float4*)(Abase + ko + 4);
#pragma unroll
            for (int i = 0; i < 4; i++)
                rb[i] = bok[i] ? W[(size_t)(ko + brow) * N + bc[i]] : 0.0f;
        }
#pragma unroll
        for (int kk = 0; kk < BBK; kk++) {
            F2U ar[4], br[4];
#pragma unroll
            for (int p = 0; p < 4; p++)
                ar[p].f = *(const float2*)&As[buf][kk][ty * 8 + p * 2];
#pragma unroll
            for (int j = 0; j < 4; j++)
                br[j].f = Bs[buf][kk][tx * 4 + j];
#pragma unroll
            for (int p = 0; p < 4; p++)
#pragma unroll
                for (int j = 0; j < 4; j++)
                    acc[p][j] = fma2(ar[p].u, br[j].u, acc[p][j]);
        }
        if (it + 1 < nT) {
            int nb = buf ^ 1;
            As[nb][akb + 0][arow] = ra0.x;  As[nb][akb + 1][arow] = ra0.y;
            As[nb][akb + 2][arow] = ra0.z;  As[nb][akb + 3][arow] = ra0.w;
            As[nb][akb + 4][arow] = ra1.x;  As[nb][akb + 5][arow] = ra1.y;
            As[nb][akb + 6][arow] = ra1.z;  As[nb][akb + 7][arow] = ra1.w;
#pragma unroll
            for (int i = 0; i < 4; i++) Bs[nb][brow][bcb + i] = make_float2(rb[i], rb[i]);
            __syncthreads();
        }
        buf ^= 1;
    }

#pragma unroll
    for (int p = 0; p < 4; p++) {
        int row0 = ty * 8 + p * 2;
#pragma unroll
        for (int j = 0; j < 4; j++) {
            int col = n0 + tx * 4 + j;
            if (col < N) {
                F2U t; t.u = acc[p][j];
                float bsv = bias[col];
                C[(size_t)row0 * N + col]       = t.f.x + bsv;
                C[(size_t)(row0 + 1) * N + col] = t.f.y + bsv;
            }
        }
    }
}

// ---------------- epilogue: sum partials + bias (+eps / relu) ----------------
struct EArgs { const float* bias; const float* eps; float* C; };

__global__ __launch_bounds__(256)
void epi_simple_kernel(EArgs e0, EArgs e1, EArgs e2, int N, int MN,
                       int ksplit, int mode, const float* part) {
    int gi = blockIdx.y;
    EArgs e = (gi == 0) ? e0 : (gi == 1) ? e1 : e2;
    int idx = blockIdx.x * 256 + threadIdx.x;
    if (idx >= MN) return;
    int col = idx % N;
    float v = e.bias[col];
    const float* P = part + (size_t)gi * ksplit * MN + idx;
    for (int kz = 0; kz < ksplit; kz++) v += P[(size_t)kz * MN];
    if (mode == 1) v += SIGMA * e.eps[idx];
    if (mode == 2) v = fmaxf(v, 0.0f);
    e.C[idx] = v;
}

// ---------------- epilogue with fused LayerNorm (N = DD = 512) ----------------
__global__ __launch_bounds__(256)
void epi_ln_kernel(const float* part, int ksplit,
                   const float* __restrict__ bias, const float* __restrict__ eps,
                   const float* __restrict__ add, const float* __restrict__ gam,
                   const float* __restrict__ bet, float* __restrict__ mid,
                   float* __restrict__ out) {
    int row = blockIdx.x;
    int tid = threadIdx.x;
    __shared__ float sh[8];
    __shared__ float s_mu, s_inv;

    int c0 = tid, c1 = tid + 256;
    float v0 = bias[c0], v1 = bias[c1];
    for (int kz = 0; kz < ksplit; kz++) {
        const float* P = part + (size_t)kz * NROW * DD + (size_t)row * DD;
        v0 += P[c0];
        v1 += P[c1];
    }
    if (eps) {
        v0 += SIGMA * eps[(size_t)row * DD + c0];
        v1 += SIGMA * eps[(size_t)row * DD + c1];
    }
    if (mid) {
        mid[(size_t)row * DD + c0] = v0;
        mid[(size_t)row * DD + c1] = v1;
    }
    float x0 = v0 + add[(size_t)row * DD + c0];
    float x1 = v1 + add[(size_t)row * DD + c1];

    float s = x0 + x1;
    float sq = x0 * x0 + x1 * x1;
#pragma unroll
    for (int o = 16; o; o >>= 1) {
        s  += __shfl_xor_sync(~0u, s, o);
        sq += __shfl_xor_sync(~0u, sq, o);
    }
    if ((tid & 31) == 0) sh[tid >> 5] = s;
    __syncthreads();
    if (tid == 0) {
        float t = 0;
        for (int i = 0; i < 8; i++) t += sh[i];
        s_mu = t / DD;
    }
    __syncthreads();
    if ((tid & 31) == 0) sh[tid >> 5] = sq;
    __syncthreads();
    if (tid == 0) {
        float t = 0;
        for (int i = 0; i < 8; i++) t += sh[i];
        float var = t / DD - s_mu * s_mu;
        s_inv = rsqrtf(var + LN_EPS);
    }
    __syncthreads();
    float mu = s_mu, inv = s_inv;
    out[(size_t)row * DD + c0] = (x0 - mu) * inv * gam[c0] + bet[c0];
    out[(size_t)row * DD + c1] = (x1 - mu) * inv * gam[c1] + bet[c1];
}

// ---------------- attention ----------------
__global__ __launch_bounds__(256)
void attn_kernel(const float* __restrict__ Kin, const float* __restrict__ Vin,
                 float* __restrict__ attnw, const int* __restrict__ tptr) {
    int t = *tptr;
    int tlen = t + 1;
    if (tlen > SS) tlen = SS;
    int bp = blockIdx.x;
    int tid = threadIdx.x;

    __shared__ float qs[DD];
    __shared__ float sc[HH][SS + 8];

    qs[tid] = g_q[bp * DD + tid];
    qs[tid + 256] = g_q[bp * DD + 256 + tid];
    __syncthreads();

    for (int idx = tid; idx < HH * tlen; idx += 256) {
        int h = idx / tlen;
        int s = idx - h * tlen;
        const float* kr = (s == t) ? &g_k[bp * DD]
                                   : &Kin[((size_t)bp * SS + s) * DD];
        const float4* k4 = (const float4*)(kr + h * DEPTH);
        const float4* q4 = (const float4*)(qs + h * DEPTH);
        float acc = 0.0f;
#pragma unroll
        for (int i = 0; i < DEPTH / 4; i++) {
            float4 kv = k4[i], qv = q4[i];
            acc += kv.x * qv.x + kv.y * qv.y + kv.z * qv.z + kv.w * qv.w;
        }
        sc[h][s] = acc * 0.125f;
    }
    __syncthreads();

    int wid = tid >> 5, lane = tid & 31;
    {
        float mx = -1e30f;
        for (int s = lane; s < tlen; s += 32) mx = fmaxf(mx, sc[wid][s]);
#pragma unroll
        for (int o = 16; o; o >>= 1) mx = fmaxf(mx, __shfl_xor_sync(~0u, mx, o));
        float sum = 0.0f;
        for (int s = lane; s < tlen; s += 32) {
            float e = __expf(sc[wid][s] - mx);
            sc[wid][s] = e;
            sum += e;
        }
#pragma unroll
        for (int o = 16; o; o >>= 1) sum += __shfl_xor_sync(~0u, sum, o);
        float r = 1.0f / sum;
        for (int s = lane; s < tlen; s += 32) sc[wid][s] *= r;
    }
    __syncthreads();

    for (int s = tid; s < SS; s += 256) {
        float v = 0.0f;
        if (s < tlen) {
#pragma unroll
            for (int h = 0; h < HH; h++) v += sc[h][s];
            v *= (1.0f / HH);
        }
        attnw[(size_t)bp * SS + s] = v;
    }

    int d0 = tid, d1 = tid + 256;
    int h0 = d0 >> 6, h1 = d1 >> 6;
    float acc0 = 0.0f, acc1 = 0.0f;
#pragma unroll 4
    for (int s = 0; s < tlen; s++) {
        const float* vr = (s == t) ? &g_v[bp * DD]
                                   : &Vin[((size_t)bp * SS + s) * DD];
        acc0 += sc[h0][s] * vr[d0];
        acc1 += sc[h1][s] * vr[d1];
    }
    g_zattn[bp * DD + d0] = acc0;
    g_zattn[bp * DD + d1] = acc1;
}

// ---------------- per-row softmax stats over VOC ----------------
__global__ __launch_bounds__(256)
void rowsoftmax_kernel(const int* __restrict__ x, float* __restrict__ wnew) {
    int row = blockIdx.x;
    const float* pr = g_pred + (size_t)row * VOC;
    int tid = threadIdx.x;
    __shared__ float sh[8];
    __shared__ float s_mx;

    float mx = -1e30f;
    for (int c = tid; c < VOC; c += 256) mx = fmaxf(mx, pr[c]);
#pragma unroll
    for (int o = 16; o; o >>= 1) mx = fmaxf(mx, __shfl_xor_sync(~0u, mx, o));
    if ((tid & 31) == 0) sh[tid >> 5] = mx;
    __syncthreads();
    if (tid == 0) {
        float m = sh[0];
        for (int i = 1; i < 8; i++) m = fmaxf(m, sh[i]);
        s_mx = m;
    }
    __syncthreads();
    mx = s_mx;
    float sum = 0.0f;
    for (int c = tid; c < VOC; c += 256) sum += __expf(pr[c] - mx);
#pragma unroll
    for (int o = 16; o; o >>= 1) sum += __shfl_xor_sync(~0u, sum, o);
    __syncthreads();
    if ((tid & 31) == 0) sh[tid >> 5] = sum;
    __syncthreads();
    if (tid == 0) {
        float sm = 0;
        for (int i = 0; i < 8; i++) sm += sh[i];
        g_rowmax[row] = mx;
        g_rowrsum[row] = 1.0f / sm;
        int b = row >> 4;
        float w = __expf(pr[x[b]] - mx) / sm;
        g_wsq[row] = w;
        wnew[row] = w;
    }
}

// ---------------- particle step: argmax_w per b, gumbel i_t ----------------
__global__ __launch_bounds__(128)
void particle_kernel(const float* __restrict__ gumbel) {
    int tid = threadIdx.x;
    int b = tid >> 4, p = tid & 15;
    __shared__ float lw[NROW];
    lw[tid] = logf(g_wsq[tid] + 1e-10f);
    __syncthreads();
    float best = -1e38f;
    int arg = 0;
    for (int j = 0; j < PP; j++) {
        float v = lw[b * PP + j] + gumbel[(b * PP + p) * PP + j];
        if (v > best) { best = v; arg = j; }
    }
    g_it[tid] = arg;
    if (p == 0) {
        float bw = g_wsq[b * PP];
        int a = 0;
        for (int j = 1; j < PP; j++)
            if (g_wsq[b * PP + j] > bw) { bw = g_wsq[b * PP + j]; a = j; }
        g_argmax[b] = a;
    }
}

// ---------------- vocab reductions ----------------
__global__ __launch_bounds__(256)
void vocab_reduce_kernel(float* __restrict__ avgs, float* __restrict__ gavg,
                         float* __restrict__ maxp) {
    int b = blockIdx.y;
    int c = blockIdx.x * 256 + threadIdx.x;
    if (c >= VOC) return;
    int am = g_argmax[b];
    float sp = 0.0f, ss = 0.0f, mp = 0.0f;
#pragma unroll
    for (int p = 0; p < PP; p++) {
        int row = b * PP + p;
        float v = g_pred[(size_t)row * VOC + c];
        sp += v;
        ss += __expf(v - g_rowmax[row]) * g_rowrsum[row];
        if (p == am) mp = v;
    }
    __stcs(&gavg[(size_t)b * VOC + c], sp * (1.0f / PP));
    __stcs(&avgs[(size_t)b * VOC + c], ss * (1.0f / PP));
    __stcs(&maxp[(size_t)b * VOC + c], mp);
}

// ---------------- misc copies / gathers ----------------
__global__ __launch_bounds__(256)
void misc_kernel(const float* __restrict__ r, const float* __restrict__ epsz,
                 const int* __restrict__ I, const int* __restrict__ tptr,
                 float* __restrict__ out) {
    int t = *tptr;
    int idx = blockIdx.x * 256 + threadIdx.x;
    out[OFF_R4 + idx] = r[idx];
    out[OFF_EPSZ + idx] = epsz[idx];
    int row = idx >> 9, d = idx & 511;
    int b = row >> 4;
    int i1 = g_it[row];
    out[OFF_Z + idx] = g_z[(b * PP + i1) * DD + d];
    int val;
    if (d < t)       val = I[(b * PP + i1) * SS + d];
    else if (d == t) val = i1;
    else             val = I[idx];
    out[OFF_INEW + idx] = (float)val;
}

// ---------------- resample K and Vs (fused) ----------------
__global__ __launch_bounds__(256)
void resample_kernel(const float* __restrict__ Kin, const int* __restrict__ tptr,
                     float* __restrict__ out) {
    int t = *tptr;
    int tid = threadIdx.x;
    int rid = blockIdx.x * 2 + (tid >> 7);
    int d4 = tid & 127;
    int s = rid & 511;
    int bp = rid >> 9;
    int b = bp >> 4;
    size_t dst = (size_t)rid * DD + d4 * 4;
    if (s > t) {
        float4 v = __ldg(&((const float4*)&Kin[((size_t)bp * SS + s) * DD])[d4]);
        __stcs((float4*)&out[OFF_K + dst], v);
        __stcs((float4*)&out[OFF_V + dst], v);
    } else {
        int i1 = g_it[bp];
        int i2 = g_it[b * PP + i1];
        const float* sk = (s == t) ? &g_k[(b * PP + i1) * DD]
                                   : &Kin[(((size_t)(b * PP + i1)) * SS + s) * DD];
        const float* sv = (s == t) ? &g_k[(b * PP + i2) * DD]
                                   : &Kin[(((size_t)(b * PP + i2)) * SS + s) * DD];
        __stcs((float4*)&out[OFF_K + dst], ((const float4*)sk)[d4]);
        __stcs((float4*)&out[OFF_V + dst], ((const float4*)sv)[d4]);
    }
}

// ---------------- launch ----------------
extern "C" void kernel_launch(void* const* d_in, const int* in_sizes, int n_in,
                              void* d_out, int out_size) {
    (void)in_sizes; (void)n_in; (void)out_size;
    const float* r      = (const float*)d_in[0];
    const int*   x      = (const int*)d_in[1];
    const float* Kin    = (const float*)d_in[2];
    const float* Vin    = (const float*)d_in[3];
    const int*   I      = (const int*)d_in[5];
    const int*   tptr   = (const int*)d_in[6];
    const float* eps_q  = (const float*)d_in[7];
    const float* eps_k  = (const float*)d_in[8];
    const float* eps_v  = (const float*)d_in[9];
    const float* eps_z  = (const float*)d_in[10];
    const float* gumbel = (const float*)d_in[11];
    const float* Wq = (const float*)d_in[12];
    const float* bq = (const float*)d_in[13];
    const float* Wk = (const float*)d_in[14];
    const float* bk = (const float*)d_in[15];
    const float* Wv = (const float*)d_in[16];
    const float* bv = (const float*)d_in[17];
    const float* Wo = (const float*)d_in[18];
    const float* bo = (const float*)d_in[19];
    const float* ln1_g = (const float*)d_in[20];
    const float* ln1_b = (const float*)d_in[21];
    const float* ln3_g = (const float*)d_in[22];
    const float* ln3_b = (const float*)d_in[23];
    const float* W1 = (const float*)d_in[24];
    const float* b1 = (const float*)d_in[25];
    const float* W2 = (const float*)d_in[26];
    const float* b2 = (const float*)d_in[27];
    const float* Wout = (const float*)d_in[28];
    const float* bout = (const float*)d_in[29];
    float* out = (float*)d_out;

    float *p_q, *p_k, *p_v, *p_zattn, *p_z, *p_out1, *p_h, *p_rr, *p_pred, *p_part;
    cudaGetSymbolAddress((void**)&p_q, g_q);
    cudaGetSymbolAddress((void**)&p_k, g_k);
    cudaGetSymbolAddress((void**)&p_v, g_v);
    cudaGetSymbolAddress((void**)&p_zattn, g_zattn);
    cudaGetSymbolAddress((void**)&p_z, g_z);
    cudaGetSymbolAddress((void**)&p_out1, g_out1);
    cudaGetSymbolAddress((void**)&p_h, g_h);
    cudaGetSymbolAddress((void**)&p_rr, g_rr);
    cudaGetSymbolAddress((void**)&p_pred, g_pred);
    cudaGetSymbolAddress((void**)&p_part, g_part);

    GArgs gz0{nullptr, nullptr, nullptr, nullptr, nullptr};

    // 1. q,k,v projections: split-K 8 -> partials, then epilogue (+bias +eps)
    {
        GArgs gq{r, Wq, bq, eps_q, p_q};
        GArgs gk{r, Wk, bk, eps_k, p_k};
        GArgs gv{r, Wv, bv, eps_v, p_v};
        gemm2_kernel<<<dim3(DD / GN, NROW / GM, 3 * 8), 256>>>(
            gq, gk, gv, NROW, DD, DD, 8, DD / 8, 1, p_part);
        EArgs eq{bq, eps_q, p_q};
        EArgs ek{bk, eps_k, p_k};
        EArgs ev{bv, eps_v, p_v};
        epi_simple_kernel<<<dim3(NROW * DD / 256, 3), 256>>>(
            eq, ek, ev, DD, NROW * DD, 8, 1, p_part);
    }
    // 2. attention
    attn_kernel<<<NROW, 256>>>(Kin, Vin, out + OFF_ATTNW, tptr);
    // 3. z = zattn @ Wo (+bo +eps_z), split-K 16, then fused epilogue+LN1
    {
        GArgs gw{p_zattn, Wo, bo, eps_z, p_z};
        gemm2_kernel<<<dim3(DD / GN, NROW / GM, 16), 256>>>(
            gw, gz0, gz0, NROW, DD, DD, 16, DD / 16, 0, p_part);
        epi_ln_kernel<<<NROW, 256>>>(p_part, 16, bo, eps_z, r, ln1_g, ln1_b,
                                     p_z, p_out1);
    }
    // 4. h = relu(out1 @ W1 + b1), split-K 4
    {
        GArgs gw{p_out1, W1, b1, nullptr, p_h};
        gemm2_kernel<<<dim3(DFF / GN, NROW / GM, 4), 256>>>(
            gw, gz0, gz0, NROW, DFF, DD, 4, DD / 4, 0, p_part);
        EArgs ef{b1, nullptr, p_h};
        epi_simple_kernel<<<dim3(NROW * DFF / 256, 1), 256>>>(
            ef, ef, ef, DFF, NROW * DFF, 4, 2, p_part);
    }
    // 5. f = h @ W2 + b2, split-K 16, fused epilogue+LN3 -> g_rr
    {
        GArgs gw{p_h, W2, b2, nullptr, p_rr};
        gemm2_kernel<<<dim3(DD / GN, NROW / GM, 16), 256>>>(
            gw, gz0, gz0, NROW, DD, DFF, 16, DFF / 16, 0, p_part);
        epi_ln_kernel<<<NROW, 256>>>(p_part, 16, b2, nullptr, p_out1,
                                     ln3_g, ln3_b, nullptr, p_rr);
    }
    // 6. predictions = r_ @ Wout + bout (dedicated big-N kernel, grid 157)
    gemm_big_kernel<<<(VOC + 63) / 64, 256>>>(p_rr, Wout, bout, p_pred, VOC, DD);
    // 7. softmax stats + w_sq
    rowsoftmax_kernel<<<NROW, 256>>>(x, out + OFF_WNEW);
    // 8. gumbel resampling indices + argmax (writes g_it / g_argmax ONCE)
    particle_kernel<<<1, 128>>>(gumbel);
    // 9. vocab reductions
    vocab_reduce_kernel<<<dim3((VOC + 255) / 256, BB), 256>>>(
        out + OFF_AVGS, out + OFF_GAVG, out + OFF_MAXP);
    // 10. misc copies + gathers
    misc_kernel<<<NROW * DD / 256, 256>>>(r, eps_z, I, tptr, out);
    // 11. resample K and Vs
    resample_kernel<<<NROW * SS / 2, 256>>>(Kin, tptr, out);
}

// round 17
// speedup vs baseline: 1.5718x; 1.1207x over previous
#include <cuda_runtime.h>
#include <cuda_bf16.h>
#include <cstdint>
#include <cstdio>

// Problem constants
#define BB 8
#define PP 16
#define SS 512
#define DD 512
#define HH 8
#define DEPTH 64
#define DFF 2048
#define VOC 10000
#define NROW 128              // B*P
#define SIGMA 0.1f
#define LN_EPS 1e-6f

// Output offsets (float elements)
static const size_t OFF_R4    = 0;
static const size_t OFF_Z     = 65536;
static const size_t OFF_AVGS  = 131072;
static const size_t OFF_GAVG  = 211072;
static const size_t OFF_MAXP  = 291072;
static const size_t OFF_EPSZ  = 371072;
static const size_t OFF_ATTNW = 436608;
static const size_t OFF_K     = 502144;
static const size_t OFF_V     = 502144ULL + 33554432ULL;
static const size_t OFF_WNEW  = 67611008ULL;
static const size_t OFF_INEW  = 67611136ULL;

// ---------------- device scratch ----------------
__device__ float g_q[NROW * DD];
__device__ float g_k[NROW * DD];
__device__ float g_v[NROW * DD];
__device__ float g_zattn[NROW * DD];
__device__ float g_z[NROW * DD];
__device__ float g_out1[NROW * DD];
__device__ float g_h[NROW * DFF];
__device__ float g_rr[NROW * DD];
__device__ float g_pred[NROW * VOC];
__device__ float g_part[3 * 4 * NROW * DD * 4];   // partial buffer
__device__ float g_rowmax[NROW];
__device__ float g_rowrsum[NROW];
__device__ float g_wsq[NROW];
__device__ int   g_it[NROW];
__device__ int   g_argmax[BB];

// ---------------- packed f32x2 helpers ----------------
union F2U { float2 f; unsigned long long u; };

__device__ __forceinline__ unsigned long long fma2(unsigned long long a,
                                                   unsigned long long b,
                                                   unsigned long long c) {
    unsigned long long d;
    asm("fma.rn.f32x2 %0, %1, %2, %3;" : "=l"(d) : "l"(a), "l"(b), "l"(c));
    return d;
}

// ---------------- GEMM v3: double-buffered split-K ----------
struct GArgs {
    const float* A;
    const float* W;
    const float* bias;
    const float* eps;
    float* C;
};

#define GM 64
#define GN 64
#define GK 32

__global__ __launch_bounds__(256, 2)
void gemm2_kernel(GArgs g0, GArgs g1, GArgs g2, int M, int N, int K,
                  int ksplit, int klen, int mode, float* part) {
    int z = blockIdx.z;
    int gi = z / ksplit, kz = z - gi * ksplit;
    GArgs g = (gi == 0) ? g0 : (gi == 1) ? g1 : g2;

    __shared__ float2 As2[2][GK][GM];   // duplicated {a,a}; 32 KB
    __shared__ float  Ws[2][GK][GN];    // 16 KB  (total 48 KB)

    int tid = threadIdx.x;
    int tx = tid & 15, ty = tid >> 4;
    int m0 = blockIdx.y * GM;
    int n0 = blockIdx.x * GN;
    int kbase = kz * klen;

    unsigned long long acc[4][2];
#pragma unroll
    for (int i = 0; i < 4; i++) { acc[i][0] = 0ULL; acc[i][1] = 0ULL; }

    int arow = tid >> 3, akq = tid & 7;
    int wkk = tid >> 4, wnq = tid & 15;

    const float* Abase0 = &g.A[(size_t)(m0 + arow) * K + kbase + akq * 4];
    const float* Abase1 = &g.A[(size_t)(m0 + 32 + arow) * K + kbase + akq * 4];
    int ncol = n0 + wnq * 4;
    bool wok = (ncol < N);
    const float* Wbase0 = &g.W[(size_t)(kbase + wkk) * N + ncol];
    const float* Wbase1 = &g.W[(size_t)(kbase + 16 + wkk) * N + ncol];

    float4 ra0, ra1, rw0, rw1;

    ra0 = *(const float4*)(Abase0);
    ra1 = *(const float4*)(Abase1);
    rw0 = wok ? *(const float4*)(Wbase0) : make_float4(0.f, 0.f, 0.f, 0.f);
    rw1 = wok ? *(const float4*)(Wbase1) : make_float4(0.f, 0.f, 0.f, 0.f);
    {
        As2[0][akq * 4 + 0][arow] = make_float2(ra0.x, ra0.x);
        As2[0][akq * 4 + 1][arow] = make_float2(ra0.y, ra0.y);
        As2[0][akq * 4 + 2][arow] = make_float2(ra0.z, ra0.z);
        As2[0][akq * 4 + 3][arow] = make_float2(ra0.w, ra0.w);
        As2[0][akq * 4 + 0][arow + 32] = make_float2(ra1.x, ra1.x);
        As2[0][akq * 4 + 1][arow + 32] = make_float2(ra1.y, ra1.y);
        As2[0][akq * 4 + 2][arow + 32] = make_float2(ra1.z, ra1.z);
        As2[0][akq * 4 + 3][arow + 32] = make_float2(ra1.w, ra1.w);
        *(float4*)&Ws[0][wkk][wnq * 4] = rw0;
        *(float4*)&Ws[0][16 + wkk][wnq * 4] = rw1;
    }
    __syncthreads();

    int nT = klen / GK;
    int buf = 0;
    for (int it = 0; it < nT; it++) {
        if (it + 1 < nT) {
            int ko = (it + 1) * GK;
            ra0 = *(const float4*)(Abase0 + ko);
            ra1 = *(const float4*)(Abase1 + ko);
            rw0 = wok ? *(const float4*)(Wbase0 + (size_t)ko * N)
                      : make_float4(0.f, 0.f, 0.f, 0.f);
            rw1 = wok ? *(const float4*)(Wbase1 + (size_t)ko * N)
                      : make_float4(0.f, 0.f, 0.f, 0.f);
        }
#pragma unroll
        for (int kk = 0; kk < GK; kk++) {
            F2U a0, a1, a2, a3, b0, b1;
            a0.f = As2[buf][kk][ty * 4 + 0];
            a1.f = As2[buf][kk][ty * 4 + 1];
            a2.f = As2[buf][kk][ty * 4 + 2];
            a3.f = As2[buf][kk][ty * 4 + 3];
            b0.f = *(const float2*)&Ws[buf][kk][tx * 4];
            b1.f = *(const float2*)&Ws[buf][kk][tx * 4 + 2];
            acc[0][0] = fma2(a0.u, b0.u, acc[0][0]);
            acc[0][1] = fma2(a0.u, b1.u, acc[0][1]);
            acc[1][0] = fma2(a1.u, b0.u, acc[1][0]);
            acc[1][1] = fma2(a1.u, b1.u, acc[1][1]);
            acc[2][0] = fma2(a2.u, b0.u, acc[2][0]);
            acc[2][1] = fma2(a2.u, b1.u, acc[2][1]);
            acc[3][0] = fma2(a3.u, b0.u, acc[3][0]);
            acc[3][1] = fma2(a3.u, b1.u, acc[3][1]);
        }
        if (it + 1 < nT) {
            int nb = buf ^ 1;
            As2[nb][akq * 4 + 0][arow] = make_float2(ra0.x, ra0.x);
            As2[nb][akq * 4 + 1][arow] = make_float2(ra0.y, ra0.y);
            As2[nb][akq * 4 + 2][arow] = make_float2(ra0.z, ra0.z);
            As2[nb][akq * 4 + 3][arow] = make_float2(ra0.w, ra0.w);
            As2[nb][akq * 4 + 0][arow + 32] = make_float2(ra1.x, ra1.x);
            As2[nb][akq * 4 + 1][arow + 32] = make_float2(ra1.y, ra1.y);
            As2[nb][akq * 4 + 2][arow + 32] = make_float2(ra1.z, ra1.z);
            As2[nb][akq * 4 + 3][arow + 32] = make_float2(ra1.w, ra1.w);
            *(float4*)&Ws[nb][wkk][wnq * 4] = rw0;
            *(float4*)&Ws[nb][16 + wkk][wnq * 4] = rw1;
            __syncthreads();
        }
        buf ^= 1;
    }

    if (ksplit > 1) {
        float* P = part + (size_t)(gi * ksplit + kz) * M * N;
#pragma unroll
        for (int i = 0; i < 4; i++) {
            int row = m0 + ty * 4 + i;
#pragma unroll
            for (int jp = 0; jp < 2; jp++) {
                int col = n0 + tx * 4 + jp * 2;
                F2U t; t.u = acc[i][jp];
                if (col < N)     P[(size_t)row * N + col] = t.f.x;
                if (col + 1 < N) P[(size_t)row * N + col + 1] = t.f.y;
            }
        }
    } else {
#pragma unroll
        for (int i = 0; i < 4; i++) {
            int row = m0 + ty * 4 + i;
#pragma unroll
            for (int jp = 0; jp < 2; jp++) {
                int col = n0 + tx * 4 + jp * 2;
                F2U t; t.u = acc[i][jp];
                if (col < N) {
                    float v = t.f.x + g.bias[col];
                    if (mode == 1) v += SIGMA * g.eps[(size_t)row * N + col];
                    if (mode == 2) v = fmaxf(v, 0.0f);
                    g.C[(size_t)row * N + col] = v;
                }
                if (col + 1 < N) {
                    float v = t.f.y + g.bias[col + 1];
                    if (mode == 1) v += SIGMA * g.eps[(size_t)row * N + col + 1];
                    if (mode == 2) v = fmaxf(v, 0.0f);
                    g.C[(size_t)row * N + col + 1] = v;
                }
            }
        }
    }
}

// ---------------- epilogue: sum partials + bias (+eps / relu) ----------------
struct EArgs { const float* bias; const float* eps; float* C; };

__global__ __launch_bounds__(256)
void epi_simple_kernel(EArgs e0, EArgs e1, EArgs e2, int N, int MN,
                       int ksplit, int mode, const float* part) {
    int gi = blockIdx.y;
    EArgs e = (gi == 0) ? e0 : (gi == 1) ? e1 : e2;
    int idx = blockIdx.x * 256 + threadIdx.x;
    if (idx >= MN) return;
    int col = idx % N;
    float v = e.bias[col];
    const float* P = part + (size_t)gi * ksplit * MN + idx;
    for (int kz = 0; kz < ksplit; kz++) v += P[(size_t)kz * MN];
    if (mode == 1) v += SIGMA * e.eps[idx];
    if (mode == 2) v = fmaxf(v, 0.0f);
    e.C[idx] = v;
}

// ---------------- epilogue with fused LayerNorm (N = DD = 512) ----------------
__global__ __launch_bounds__(256)
void epi_ln_kernel(const float* part, int ksplit,
                   const float* __restrict__ bias, const float* __restrict__ eps,
                   const float* __restrict__ add, const float* __restrict__ gam,
                   const float* __restrict__ bet, float* __restrict__ mid,
                   float* __restrict__ out) {
    int row = blockIdx.x;
    int tid = threadIdx.x;
    __shared__ float sh[8];
    __shared__ float s_mu, s_inv;

    int c0 = tid, c1 = tid + 256;
    float v0 = bias[c0], v1 = bias[c1];
    for (int kz = 0; kz < ksplit; kz++) {
        const float* P = part + (size_t)kz * NROW * DD + (size_t)row * DD;
        v0 += P[c0];
        v1 += P[c1];
    }
    if (eps) {
        v0 += SIGMA * eps[(size_t)row * DD + c0];
        v1 += SIGMA * eps[(size_t)row * DD + c1];
    }
    if (mid) {
        mid[(size_t)row * DD + c0] = v0;
        mid[(size_t)row * DD + c1] = v1;
    }
    float x0 = v0 + add[(size_t)row * DD + c0];
    float x1 = v1 + add[(size_t)row * DD + c1];

    float s = x0 + x1;
    float sq = x0 * x0 + x1 * x1;
#pragma unroll
    for (int o = 16; o; o >>= 1) {
        s  += __shfl_xor_sync(~0u, s, o);
        sq += __shfl_xor_sync(~0u, sq, o);
    }
    if ((tid & 31) == 0) sh[tid >> 5] = s;
    __syncthreads();
    if (tid == 0) {
        float t = 0;
        for (int i = 0; i < 8; i++) t += sh[i];
        s_mu = t / DD;
    }
    __syncthreads();
    if ((tid & 31) == 0) sh[tid >> 5] = sq;
    __syncthreads();
    if (tid == 0) {
        float t = 0;
        for (int i = 0; i < 8; i++) t += sh[i];
        float var = t / DD - s_mu * s_mu;
        s_inv = rsqrtf(var + LN_EPS);
    }
    __syncthreads();
    float mu = s_mu, inv = s_inv;
    out[(size_t)row * DD + c0] = (x0 - mu) * inv * gam[c0] + bet[c0];
    out[(size_t)row * DD + c1] = (x1 - mu) * inv * gam[c1] + bet[c1];
}

// ---------------- attention ----------------
__global__ __launch_bounds__(256)
void attn_kernel(const float* __restrict__ Kin, const float* __restrict__ Vin,
                 float* __restrict__ attnw, const int* __restrict__ tptr) {
    int t = *tptr;
    int tlen = t + 1;
    if (tlen > SS) tlen = SS;
    int bp = blockIdx.x;
    int tid = threadIdx.x;

    __shared__ float qs[DD];
    __shared__ float sc[HH][SS + 8];

    qs[tid] = g_q[bp * DD + tid];
    qs[tid + 256] = g_q[bp * DD + 256 + tid];
    __syncthreads();

    for (int idx = tid; idx < HH * tlen; idx += 256) {
        int h = idx / tlen;
        int s = idx - h * tlen;
        const float* kr = (s == t) ? &g_k[bp * DD]
                                   : &Kin[((size_t)bp * SS + s) * DD];
        const float4* k4 = (const float4*)(kr + h * DEPTH);
        const float4* q4 = (const float4*)(qs + h * DEPTH);
        float acc = 0.0f;
#pragma unroll
        for (int i = 0; i < DEPTH / 4; i++) {
            float4 kv = k4[i], qv = q4[i];
            acc += kv.x * qv.x + kv.y * qv.y + kv.z * qv.z + kv.w * qv.w;
        }
        sc[h][s] = acc * 0.125f;
    }
    __syncthreads();

    int wid = tid >> 5, lane = tid & 31;
    {
        float mx = -1e30f;
        for (int s = lane; s < tlen; s += 32) mx = fmaxf(mx, sc[wid][s]);
#pragma unroll
        for (int o = 16; o; o >>= 1) mx = fmaxf(mx, __shfl_xor_sync(~0u, mx, o));
        float sum = 0.0f;
        for (int s = lane; s < tlen; s += 32) {
            float e = __expf(sc[wid][s] - mx);
            sc[wid][s] = e;
            sum += e;
        }
#pragma unroll
        for (int o = 16; o; o >>= 1) sum += __shfl_xor_sync(~0u, sum, o);
        float r = 1.0f / sum;
        for (int s = lane; s < tlen; s += 32) sc[wid][s] *= r;
    }
    __syncthreads();

    for (int s = tid; s < SS; s += 256) {
        float v = 0.0f;
        if (s < tlen) {
#pragma unroll
            for (int h = 0; h < HH; h++) v += sc[h][s];
            v *= (1.0f / HH);
        }
        attnw[(size_t)bp * SS + s] = v;
    }

    int d0 = tid, d1 = tid + 256;
    int h0 = d0 >> 6, h1 = d1 >> 6;
    float acc0 = 0.0f, acc1 = 0.0f;
#pragma unroll 4
    for (int s = 0; s < tlen; s++) {
        const float* vr = (s == t) ? &g_v[bp * DD]
                                   : &Vin[((size_t)bp * SS + s) * DD];
        acc0 += sc[h0][s] * vr[d0];
        acc1 += sc[h1][s] * vr[d1];
    }
    g_zattn[bp * DD + d0] = acc0;
    g_zattn[bp * DD + d1] = acc1;
}

// ---------------- per-row softmax stats over VOC ----------------
__global__ __launch_bounds__(256)
void rowsoftmax_kernel(const int* __restrict__ x, float* __restrict__ wnew) {
    int row = blockIdx.x;
    const float* pr = g_pred + (size_t)row * VOC;
    int tid = threadIdx.x;
    __shared__ float sh[8];
    __shared__ float s_mx;

    float mx = -1e30f;
    for (int c = tid; c < VOC; c += 256) mx = fmaxf(mx, pr[c]);
#pragma unroll
    for (int o = 16; o; o >>= 1) mx = fmaxf(mx, __shfl_xor_sync(~0u, mx, o));
    if ((tid & 31) == 0) sh[tid >> 5] = mx;
    __syncthreads();
    if (tid == 0) {
        float m = sh[0];
        for (int i = 1; i < 8; i++) m = fmaxf(m, sh[i]);
        s_mx = m;
    }
    __syncthreads();
    mx = s_mx;
    float sum = 0.0f;
    for (int c = tid; c < VOC; c += 256) sum += __expf(pr[c] - mx);
#pragma unroll
    for (int o = 16; o; o >>= 1) sum += __shfl_xor_sync(~0u, sum, o);
    __syncthreads();
    if ((tid & 31) == 0) sh[tid >> 5] = sum;
    __syncthreads();
    if (tid == 0) {
        float sm = 0;
        for (int i = 0; i < 8; i++) sm += sh[i];
        g_rowmax[row] = mx;
        g_rowrsum[row] = 1.0f / sm;
        int b = row >> 4;
        float w = __expf(pr[x[b]] - mx) / sm;
        g_wsq[row] = w;
        wnew[row] = w;
    }
}

// ---------------- particle step: argmax_w per b, gumbel i_t ----------------
__global__ __launch_bounds__(128)
void particle_kernel(const float* __restrict__ gumbel) {
    int tid = threadIdx.x;
    int b = tid >> 4, p = tid & 15;
    __shared__ float lw[NROW];
    lw[tid] = logf(g_wsq[tid] + 1e-10f);
    __syncthreads();
    float best = -1e38f;
    int arg = 0;
    for (int j = 0; j < PP; j++) {
        float v = lw[b * PP + j] + gumbel[(b * PP + p) * PP + j];
        if (v > best) { best = v; arg = j; }
    }
    g_it[tid] = arg;
    if (p == 0) {
        float bw = g_wsq[b * PP];
        int a = 0;
        for (int j = 1; j < PP; j++)
            if (g_wsq[b * PP + j] > bw) { bw = g_wsq[b * PP + j]; a = j; }
        g_argmax[b] = a;
    }
}

// ---------------- vocab reductions ----------------
__global__ __launch_bounds__(256)
void vocab_reduce_kernel(float* __restrict__ avgs, float* __restrict__ gavg,
                         float* __restrict__ maxp) {
    int b = blockIdx.y;
    int c = blockIdx.x * 256 + threadIdx.x;
    if (c >= VOC) return;
    int am = g_argmax[b];
    float sp = 0.0f, ss = 0.0f, mp = 0.0f;
#pragma unroll
    for (int p = 0; p < PP; p++) {
        int row = b * PP + p;
        float v = g_pred[(size_t)row * VOC + c];
        sp += v;
        ss += __expf(v - g_rowmax[row]) * g_rowrsum[row];
        if (p == am) mp = v;
    }
    __stcs(&gavg[(size_t)b * VOC + c], sp * (1.0f / PP));
    __stcs(&avgs[(size_t)b * VOC + c], ss * (1.0f / PP));
    __stcs(&maxp[(size_t)b * VOC + c], mp);
}

// ---------------- misc gathers (g_it-dependent only) ----------------
__global__ __launch_bounds__(256)
void misc_kernel(const int* __restrict__ I, const int* __restrict__ tptr,
                 float* __restrict__ out) {
    int t = *tptr;
    int idx = blockIdx.x * 256 + threadIdx.x;
    int row = idx >> 9, d = idx & 511;
    int b = row >> 4;
    int i1 = g_it[row];
    out[OFF_Z + idx] = g_z[(b * PP + i1) * DD + d];
    int val;
    if (d < t)       val = I[(b * PP + i1) * SS + d];
    else if (d == t) val = i1;
    else             val = I[idx];
    out[OFF_INEW + idx] = (float)val;
}

// ---------------- static copies: K/Vs rows s>t + r4/eps_z ----------------
#define NRES_BLK (NROW * SS / 2)   // 32768
#define NCPY_BLK 64                // 65536 floats / (256 thr * 4)

__global__ __launch_bounds__(256)
void static_kernel(const float* __restrict__ Kin, const float* __restrict__ r,
                   const float* __restrict__ epsz, const int* __restrict__ tptr,
                   float* __restrict__ out) {
    int bid = blockIdx.x;
    int tid = threadIdx.x;
    if (bid < NRES_BLK) {
        int t = *tptr;
        int rid = bid * 2 + (tid >> 7);
        int s = rid & 511;
        if (s <= t) return;
        int d4 = tid & 127;
        int bp = rid >> 9;
        size_t dst = (size_t)rid * DD + d4 * 4;
        float4 v = __ldg(&((const float4*)&Kin[((size_t)bp * SS + s) * DD])[d4]);
        __stcs((float4*)&out[OFF_K + dst], v);
        __stcs((float4*)&out[OFF_V + dst], v);
    } else {
        int idx4 = (bid - NRES_BLK) * 256 + tid;   // float4 index, 16384 total
        float4 rv = ((const float4*)r)[idx4];
        float4 ev = ((const float4*)epsz)[idx4];
        ((float4*)&out[OFF_R4])[idx4] = rv;
        ((float4*)&out[OFF_EPSZ])[idx4] = ev;
    }
}

// ---------------- dynamic resample: rows s <= t (needs g_it, g_k) ----------
__global__ __launch_bounds__(256)
void resample_kernel(const float* __restrict__ Kin, const int* __restrict__ tptr,
                     float* __restrict__ out) {
    int t = *tptr;
    int tid = threadIdx.x;
    int rid = blockIdx.x * 2 + (tid >> 7);
    int s = rid & 511;
    if (s > t) return;
    int d4 = tid & 127;
    int bp = rid >> 9;
    int b = bp >> 4;
    size_t dst = (size_t)rid * DD + d4 * 4;
    int i1 = g_it[bp];
    int i2 = g_it[b * PP + i1];
    const float* sk = (s == t) ? &g_k[(b * PP + i1) * DD]
                               : &Kin[(((size_t)(b * PP + i1)) * SS + s) * DD];
    const float* sv = (s == t) ? &g_k[(b * PP + i2) * DD]
                               : &Kin[(((size_t)(b * PP + i2)) * SS + s) * DD];
    __stcs((float4*)&out[OFF_K + dst], ((const float4*)sk)[d4]);
    __stcs((float4*)&out[OFF_V + dst], ((const float4*)sv)[d4]);
}

// ---------------- launch ----------------
extern "C" void kernel_launch(void* const* d_in, const int* in_sizes, int n_in,
                              void* d_out, int out_size) {
    (void)in_sizes; (void)n_in; (void)out_size;
    const float* r      = (const float*)d_in[0];
    const int*   x      = (const int*)d_in[1];
    const float* Kin    = (const float*)d_in[2];
    const float* Vin    = (const float*)d_in[3];
    const int*   I      = (const int*)d_in[5];
    const int*   tptr   = (const int*)d_in[6];
    const float* eps_q  = (const float*)d_in[7];
    const float* eps_k  = (const float*)d_in[8];
    const float* eps_v  = (const float*)d_in[9];
    const float* eps_z  = (const float*)d_in[10];
    const float* gumbel = (const float*)d_in[11];
    const float* Wq = (const float*)d_in[12];
    const float* bq = (const float*)d_in[13];
    const float* Wk = (const float*)d_in[14];
    const float* bk = (const float*)d_in[15];
    const float* Wv = (const float*)d_in[16];
    const float* bv = (const float*)d_in[17];
    const float* Wo = (const float*)d_in[18];
    const float* bo = (const float*)d_in[19];
    const float* ln1_g = (const float*)d_in[20];
    const float* ln1_b = (const float*)d_in[21];
    const float* ln3_g = (const float*)d_in[22];
    const float* ln3_b = (const float*)d_in[23];
    const float* W1 = (const float*)d_in[24];
    const float* b1 = (const float*)d_in[25];
    const float* W2 = (const float*)d_in[26];
    const float* b2 = (const float*)d_in[27];
    const float* Wout = (const float*)d_in[28];
    const float* bout = (const float*)d_in[29];
    float* out = (float*)d_out;

    float *p_q, *p_k, *p_v, *p_zattn, *p_z, *p_out1, *p_h, *p_rr, *p_pred, *p_part;
    cudaGetSymbolAddress((void**)&p_q, g_q);
    cudaGetSymbolAddress((void**)&p_k, g_k);
    cudaGetSymbolAddress((void**)&p_v, g_v);
    cudaGetSymbolAddress((void**)&p_zattn, g_zattn);
    cudaGetSymbolAddress((void**)&p_z, g_z);
    cudaGetSymbolAddress((void**)&p_out1, g_out1);
    cudaGetSymbolAddress((void**)&p_h, g_h);
    cudaGetSymbolAddress((void**)&p_rr, g_rr);
    cudaGetSymbolAddress((void**)&p_pred, g_pred);
    cudaGetSymbolAddress((void**)&p_part, g_part);

    // Side stream + events (created once; host-side objects only)
    static cudaStream_t s1 = nullptr;
    static cudaEvent_t ev_fork = nullptr, ev_join = nullptr;
    if (s1 == nullptr) {
        cudaStreamCreateWithFlags(&s1, cudaStreamNonBlocking);
        cudaEventCreateWithFlags(&ev_fork, cudaEventDisableTiming);
        cudaEventCreateWithFlags(&ev_join, cudaEventDisableTiming);
    }

    GArgs gz0{nullptr, nullptr, nullptr, nullptr, nullptr};

    // 0. fork: static copies (K/Vs s>t rows + r4/eps_z) on side stream,
    //    concurrent with the latency-bound GEMM chain below.
    cudaEventRecord(ev_fork, 0);
    cudaStreamWaitEvent(s1, ev_fork, 0);
    static_kernel<<<NRES_BLK + NCPY_BLK, 256, 0, s1>>>(Kin, r, eps_z, tptr, out);
    cudaEventRecord(ev_join, s1);

    // 1. q,k,v projections: split-K 8 -> partials, then epilogue (+bias +eps)
    {
        GArgs gq{r, Wq, bq, eps_q, p_q};
        GArgs gk{r, Wk, bk, eps_k, p_k};
        GArgs gv{r, Wv, bv, eps_v, p_v};
        gemm2_kernel<<<dim3(DD / GN, NROW / GM, 3 * 8), 256>>>(
            gq, gk, gv, NROW, DD, DD, 8, DD / 8, 1, p_part);
        EArgs eq{bq, eps_q, p_q};
        EArgs ek{bk, eps_k, p_k};
        EArgs ev{bv, eps_v, p_v};
        epi_simple_kernel<<<dim3(NROW * DD / 256, 3), 256>>>(
            eq, ek, ev, DD, NROW * DD, 8, 1, p_part);
    }
    // 2. attention
    attn_kernel<<<NROW, 256>>>(Kin, Vin, out + OFF_ATTNW, tptr);
    // 3. z = zattn @ Wo (+bo +eps_z), split-K 16, then fused epilogue+LN1
    {
        GArgs gw{p_zattn, Wo, bo, eps_z, p_z};
        gemm2_kernel<<<dim3(DD / GN, NROW / GM, 16), 256>>>(
            gw, gz0, gz0, NROW, DD, DD, 16, DD / 16, 0, p_part);
        epi_ln_kernel<<<NROW, 256>>>(p_part, 16, bo, eps_z, r, ln1_g, ln1_b,
                                     p_z, p_out1);
    }
    // 4. h = relu(out1 @ W1 + b1), split-K 4
    {
        GArgs gw{p_out1, W1, b1, nullptr, p_h};
        gemm2_kernel<<<dim3(DFF / GN, NROW / GM, 4), 256>>>(
            gw, gz0, gz0, NROW, DFF, DD, 4, DD / 4, 0, p_part);
        EArgs ef{b1, nullptr, p_h};
        epi_simple_kernel<<<dim3(NROW * DFF / 256, 1), 256>>>(
            ef, ef, ef, DFF, NROW * DFF, 4, 2, p_part);
    }
    // 5. f = h @ W2 + b2, split-K 16, fused epilogue+LN3 -> g_rr
    {
        GArgs gw{p_h, W2, b2, nullptr, p_rr};
        gemm2_kernel<<<dim3(DD / GN, NROW / GM, 16), 256>>>(
            gw, gz0, gz0, NROW, DD, DFF, 16, DFF / 16, 0, p_part);
        epi_ln_kernel<<<NROW, 256>>>(p_part, 16, b2, nullptr, p_out1,
                                     ln3_g, ln3_b, nullptr, p_rr);
    }
    // 6. predictions = r_ @ Wout + bout (gemm2 direct write, grid 314)
    {
        GArgs gw{p_rr, Wout, bout, nullptr, p_pred};
        gemm2_kernel<<<dim3((VOC + GN - 1) / GN, NROW / GM, 1), 256>>>(
            gw, gz0, gz0, NROW, VOC, DD, 1, DD, 0, p_part);
    }
    // 7. softmax stats + w_sq
    rowsoftmax_kernel<<<NROW, 256>>>(x, out + OFF_WNEW);
    // 8. gumbel resampling indices + argmax (writes g_it / g_argmax ONCE)
    particle_kernel<<<1, 128>>>(gumbel);
    // 9. vocab reductions
    vocab_reduce_kernel<<<dim3((VOC + 255) / 256, BB), 256>>>(
        out + OFF_AVGS, out + OFF_GAVG, out + OFF_MAXP);
    // 10. misc gathers (z, I_new)
    misc_kernel<<<NROW * DD / 256, 256>>>(I, tptr, out);
    // 11. dynamic resample (s <= t rows)
    resample_kernel<<<NROW * SS / 2, 256>>>(Kin, tptr, out);
    // 12. join side stream
    cudaStreamWaitEvent(0, ev_join, 0);
}